// round 13
// baseline (speedup 1.0000x reference)
#include <cuda_runtime.h>
#include <cuda_fp16.h>
#include <cstdint>

// Shapes fixed by the reference
#define N_NODES  100000
#define IN_DIM   128
#define KDIM     256          // 2*IN_DIM
#define HID      64
#define WARPS    6            // warps per block (one block per SM)
#define NTHREADS (WARPS*32)
#define CHUNK_E  32           // edges per warp chunk (M=32)
#define GRID     152          // 1 block per SM

// Skewed layouts (no padding): word col' = (col + 4*row) & 127
#define A_SLAB_BYTES  (32*512)                 // 16 KB per buffer
#define SMEM_AS       0
#define SMEM_W1       (WARPS*2*A_SLAB_BYTES)   // 192 KB
#define SMEM_B1       (SMEM_W1 + 64*512)       // W1: 64 rows x 512 B = 32 KB
#define SMEM_W2       (SMEM_B1 + 256)
#define SMEM_B2       (SMEM_W2 + 256)
#define SMEM_BYTES    (SMEM_B2 + 16)

// fp16 copy of z, gathered via cp.async (25.6 MB static scratch)
__device__ __half zh_g[N_NODES * IN_DIM];

__global__ void convert_z_kernel(const float* __restrict__ z, int n) {
    const int stride = gridDim.x * blockDim.x;
    const int n4 = n >> 2;
    const float4* z4 = reinterpret_cast<const float4*>(z);
    __half2* o2 = reinterpret_cast<__half2*>(zh_g);
    for (int i = blockIdx.x * blockDim.x + threadIdx.x; i < n4; i += stride) {
        float4 v = z4[i];
        o2[i * 2 + 0] = __floats2half2_rn(v.x, v.y);
        o2[i * 2 + 1] = __floats2half2_rn(v.z, v.w);
    }
}

__device__ __forceinline__ void mma_fp16(float* c, const uint32_t* a,
                                         uint32_t b0, uint32_t b1) {
    asm volatile(
        "mma.sync.aligned.m16n8k16.row.col.f32.f16.f16.f32 "
        "{%0,%1,%2,%3}, {%4,%5,%6,%7}, {%8,%9}, {%0,%1,%2,%3};"
        : "+f"(c[0]), "+f"(c[1]), "+f"(c[2]), "+f"(c[3])
        : "r"(a[0]), "r"(a[1]), "r"(a[2]), "r"(a[3]), "r"(b0), "r"(b1));
}

struct GatherCtx {
    const int* e32;
    const long long* e64;
    bool is64;
    const char* zb;
    int NE, lane, sub, j;     // j = logical 16B chunk (0..31) this lane writes
};

// Issue cp.async gather of one 32-edge chunk into slab at smem addr `abase`.
// Skewed dst: row i, chunk j -> byte off i*512 + 16*((j + i) & 31).
__device__ __forceinline__ void issue_gather(const GatherCtx& c, int chunk,
                                             uint32_t abase) {
    const int ge = chunk * CHUNK_E + c.lane;
    long long sIdx = 0, dIdx = 0;
    if (ge < c.NE) {
        if (c.is64) { sIdx = c.e64[ge]; dIdx = c.e64[(long long)c.NE + ge]; }
        else        { sIdx = (long long)c.e32[ge]; dIdx = (long long)c.e32[c.NE + ge]; }
    }
    const bool useDst = (c.j >= 16);
    const int coff = c.sub * 16;
    #pragma unroll 8
    for (int i = 0; i < 32; i++) {
        const long long s = __shfl_sync(0xffffffffu, sIdx, i);
        const long long d = __shfl_sync(0xffffffffu, dIdx, i);
        const long long row = useDst ? d : s;
        const char* src = c.zb + (row << 8) + coff;
        const uint32_t daddr = abase + (uint32_t)(i * 512 + 16 * ((c.j + i) & 31));
        asm volatile("cp.async.cg.shared.global [%0], [%1], 16;\n"
                     :: "r"(daddr), "l"(src));
    }
    asm volatile("cp.async.commit_group;\n");
}

__global__ __launch_bounds__(NTHREADS, 1)
void mask_predictor_kernel(const void* __restrict__ eidx_raw,
                           const float* __restrict__ W1,
                           const float* __restrict__ b1,
                           const float* __restrict__ W2,
                           const float* __restrict__ b2,
                           float* __restrict__ out,
                           int NE) {
    extern __shared__ unsigned char smem_raw[];
    uint32_t* W1t32 = reinterpret_cast<uint32_t*>(smem_raw + SMEM_W1);
    __half*   W1th  = reinterpret_cast<__half*>(smem_raw + SMEM_W1);
    float*    b1s   = reinterpret_cast<float*>(smem_raw + SMEM_B1);
    float*    w2s   = reinterpret_cast<float*>(smem_raw + SMEM_W2);
    float*    b2s   = reinterpret_cast<float*>(smem_raw + SMEM_B2);

    const int tid  = threadIdx.x;
    const int warp = tid >> 5;
    const int lane = tid & 31;
    const int g    = lane >> 2;   // groupID (0..7)
    const int m    = lane & 3;    // thread-in-group (0..3)

    // ---- Detect edge_index dtype (int64 vs int32) uniformly ----
    const int*       e32 = reinterpret_cast<const int*>(eidx_raw);
    const long long* e64 = reinterpret_cast<const long long*>(eidx_raw);
    bool is64 = true;
    #pragma unroll
    for (int i = 1; i < 32; i += 2) if (e32[i] != 0) is64 = false;

    // ---- Stage W1^T (fp16) with skewed layout; biases ----
    // Element W1[k][n] -> row n, half col k; stored word col = ((k>>1)+4n)&127.
    for (int i = tid; i < KDIM * HID; i += NTHREADS) {
        const int k = i >> 6, n = i & 63;
        const int sw = (((k >> 1) + 4 * n) & 127) * 2 + (k & 1);
        W1th[n * 256 + sw] = __float2half(W1[i]);
    }
    if (tid < 64) { b1s[tid] = b1[tid]; w2s[tid] = W2[tid]; }
    if (tid == 64) { b2s[0] = b2[0]; }
    __syncthreads();

    // Per-warp double-buffered A slabs (shared-space addresses)
    const uint32_t asBase =
        (uint32_t)__cvta_generic_to_shared(smem_raw + SMEM_AS);
    const uint32_t abuf0 = asBase + (warp * 2 + 0) * A_SLAB_BYTES;
    const uint32_t abuf1 = asBase + (warp * 2 + 1) * A_SLAB_BYTES;
    uint32_t* slab0 = reinterpret_cast<uint32_t*>(smem_raw + SMEM_AS
                                                  + (warp * 2 + 0) * A_SLAB_BYTES);
    uint32_t* slab1 = reinterpret_cast<uint32_t*>(smem_raw + SMEM_AS
                                                  + (warp * 2 + 1) * A_SLAB_BYTES);

    GatherCtx ctx;
    ctx.e32 = e32; ctx.e64 = e64; ctx.is64 = is64;
    ctx.zb = reinterpret_cast<const char*>(zh_g);
    ctx.NE = NE;
    ctx.lane = lane;
    ctx.sub = lane & 15;
    ctx.j = lane;   // logical chunk = halfSel*16 + sub = lane

    const int nChunks = (NE + CHUNK_E - 1) / CHUNK_E;
    const int wStride = GRID * WARPS;

    // Per-warp pipeline: one gather group always in flight; the wait at loop
    // top has had a full chunk's compute time to complete -> near-zero stall.
    int chunk = blockIdx.x * WARPS + warp;
    int buf = 0;
    if (chunk < nChunks) issue_gather(ctx, chunk, abuf0);

    for (; chunk < nChunks; chunk += wStride) {
        const int nxt = chunk + wStride;
        if (nxt < nChunks) {
            issue_gather(ctx, nxt, buf ? abuf0 : abuf1);
            asm volatile("cp.async.wait_group 1;\n" ::: "memory");
        } else {
            asm volatile("cp.async.wait_group 0;\n" ::: "memory");
        }
        __syncwarp();   // make lane-written rows visible warp-wide

        uint32_t* myAs = buf ? slab1 : slab0;

        // ---- GEMM: 32 edges x 64 cols, fp16 m16n8k16, fp32 acc ----
        float acc[2][8][4];
        #pragma unroll
        for (int mt = 0; mt < 2; mt++)
            #pragma unroll
            for (int nt = 0; nt < 8; nt++)
                #pragma unroll
                for (int r = 0; r < 4; r++) acc[mt][nt][r] = 0.f;

        #pragma unroll 4
        for (int kt = 0; kt < 16; kt++) {
            const int kw = kt * 8 + m;
            uint32_t a[2][4];
            #pragma unroll
            for (int mt = 0; mt < 2; mt++) {
                const int r0 = mt * 16 + g;
                const int r1 = r0 + 8;
                a[mt][0] = myAs[r0 * 128 + ((kw + 4 * r0) & 127)];
                a[mt][1] = myAs[r1 * 128 + ((kw + 4 * r1) & 127)];
                a[mt][2] = myAs[r0 * 128 + ((kw + 4 + 4 * r0) & 127)];
                a[mt][3] = myAs[r1 * 128 + ((kw + 4 + 4 * r1) & 127)];
            }
            #pragma unroll
            for (int nt = 0; nt < 8; nt++) {
                const int n = nt * 8 + g;
                const uint32_t b0  = W1t32[n * 128 + ((kw + 4 * n) & 127)];
                const uint32_t b1v = W1t32[n * 128 + ((kw + 4 + 4 * n) & 127)];
                mma_fp16(acc[0][nt], a[0], b0, b1v);
                mma_fp16(acc[1][nt], a[1], b0, b1v);
            }
        }

        // ---- Epilogue: bias + ReLU + W2 dot + sigmoid ----
        float p[4] = {0.f, 0.f, 0.f, 0.f};  // rows g, g+8, g+16, g+24
        #pragma unroll
        for (int mt = 0; mt < 2; mt++) {
            #pragma unroll
            for (int nt = 0; nt < 8; nt++) {
                const int c = nt * 8 + 2 * m;
                const float ba = b1s[c], bb = b1s[c + 1];
                const float wa = w2s[c], wb = w2s[c + 1];
                float h;
                h = acc[mt][nt][0] + ba; p[mt * 2 + 0] += fmaxf(h, 0.f) * wa;
                h = acc[mt][nt][1] + bb; p[mt * 2 + 0] += fmaxf(h, 0.f) * wb;
                h = acc[mt][nt][2] + ba; p[mt * 2 + 1] += fmaxf(h, 0.f) * wa;
                h = acc[mt][nt][3] + bb; p[mt * 2 + 1] += fmaxf(h, 0.f) * wb;
            }
        }
        #pragma unroll
        for (int j = 0; j < 4; j++) {
            p[j] += __shfl_xor_sync(0xffffffffu, p[j], 1);
            p[j] += __shfl_xor_sync(0xffffffffu, p[j], 2);
        }
        if (m == 0) {
            const float bias2 = b2s[0];
            const int base = chunk * CHUNK_E;
            #pragma unroll
            for (int j = 0; j < 4; j++) {
                const int e = base + (j >> 1) * 16 + (j & 1) * 8 + g;
                if (e < NE)
                    out[e] = 1.f / (1.f + __expf(-(p[j] + bias2)));
            }
        }
        buf ^= 1;
    }
}

extern "C" void kernel_launch(void* const* d_in, const int* in_sizes, int n_in,
                              void* d_out, int out_size) {
    const float* z    = (const float*)d_in[0];
    const void*  eidx = d_in[1];
    const float* W1   = (const float*)d_in[2];
    const float* b1   = (const float*)d_in[3];
    const float* W2   = (const float*)d_in[4];
    const float* b2   = (const float*)d_in[5];
    float*       out  = (float*)d_out;

    const int NE = in_sizes[1] / 2;  // edge_index is (2, E)
    const int nZ = in_sizes[0];      // N_NODES * IN_DIM

    static bool attr_set = false;
    if (!attr_set) {
        cudaFuncSetAttribute(mask_predictor_kernel,
                             cudaFuncAttributeMaxDynamicSharedMemorySize, SMEM_BYTES);
        attr_set = true;
    }

    convert_z_kernel<<<152, 256>>>(z, nZ);
    mask_predictor_kernel<<<GRID, NTHREADS, SMEM_BYTES>>>(eidx, W1, b1, W2, b2, out, NE);
}